// round 1
// baseline (speedup 1.0000x reference)
#include <cuda_runtime.h>
#include <math.h>

#define HH 128
#define WW 128
#define CC 64
#define OO 64
#define BB 4
#define K2 9
#define HW (HH*WW)

// Scratch (no allocations allowed)
__device__ float g_off[BB * 18 * HW];      // offsets [b][18][H][W]
__device__ float g_mod[BB * HW];           // mod_mean [b][H][W]
__device__ float g_wT[K2 * CC * OO];       // weight transposed [k][c][o]

// ---------------------------------------------------------------------------
// K0: weight transpose  w[o][c][k] -> wT[k][c][o]
// ---------------------------------------------------------------------------
__global__ void k_transpose(const float* __restrict__ w) {
    int idx = blockIdx.x * 256 + threadIdx.x;   // 36864 total
    if (idx < OO * CC * K2) {
        int o = idx / (CC * K2);
        int c = (idx / K2) % CC;
        int k = idx % K2;
        g_wT[(k * CC + c) * OO + o] = w[idx];
    }
}

// ---------------------------------------------------------------------------
// K1: offsets (18ch) + modulation mean (sigmoid-mean of 9ch), 3x3 conv pad=1
// Block: 256 threads, tile 16 rows x 32 cols, 2 pixels/thread (j, j+16)
// Grid: (128/32, 128/16, B) = (4, 8, 4)
// ---------------------------------------------------------------------------
__global__ __launch_bounds__(256) void k_offmod(
    const float* __restrict__ x,
    const float* __restrict__ ow, const float* __restrict__ ob,
    const float* __restrict__ mw, const float* __restrict__ mb)
{
    __shared__ float s_wk[27 * 64];
    __shared__ float s_b[27];

    int tid = threadIdx.x;
    int b = blockIdx.z;
    int i0 = blockIdx.y * 16;
    int j0 = blockIdx.x * 32;
    int tx = tid & 15, ty = tid >> 4;
    int i  = i0 + ty;
    int ja = j0 + tx;
    int jb = j0 + 16 + tx;

    if (tid < 27) s_b[tid] = (tid < 18) ? ob[tid] : mb[tid - 18];

    const float* xb = x + (size_t)b * CC * HW;

    float acc[54];
#pragma unroll
    for (int m = 0; m < 54; m++) acc[m] = 0.f;

    for (int k = 0; k < 9; k++) {
        __syncthreads();
        // stage weight slice for this k: s_wk[m*64+c]
        for (int idx = tid; idx < 27 * 64; idx += 256) {
            int m = idx >> 6, c = idx & 63;
            s_wk[idx] = (m < 18) ? ow[m * 576 + c * 9 + k]
                                 : mw[(m - 18) * 576 + c * 9 + k];
        }
        __syncthreads();

        int dy = k / 3 - 1, dx = k % 3 - 1;
        int yy = i + dy;
        bool yok = (yy >= 0) && (yy < HH);
        int xa = ja + dx, xbp = jb + dx;
        bool aok = yok && (xa >= 0) && (xa < WW);
        bool bok = yok && (xbp >= 0) && (xbp < WW);
        const float* xrow = xb + yy * WW;

        for (int c = 0; c < CC; c++) {
            float va = aok ? __ldg(xrow + c * HW + xa)  : 0.f;
            float vb = bok ? __ldg(xrow + c * HW + xbp) : 0.f;
#pragma unroll
            for (int m = 0; m < 27; m++) {
                float wv = s_wk[m * 64 + c];
                acc[m * 2]     = fmaf(va, wv, acc[m * 2]);
                acc[m * 2 + 1] = fmaf(vb, wv, acc[m * 2 + 1]);
            }
        }
    }

    // write offsets
    float* offb = g_off + (size_t)b * 18 * HW;
#pragma unroll
    for (int m = 0; m < 18; m++) {
        float bv = s_b[m];
        offb[m * HW + i * WW + ja] = acc[m * 2] + bv;
        offb[m * HW + i * WW + jb] = acc[m * 2 + 1] + bv;
    }
    // modulation mean (mean over 9 channels of sigmoid)
    float sa = 0.f, sb2 = 0.f;
#pragma unroll
    for (int m = 18; m < 27; m++) {
        float bv = s_b[m];
        sa  += 1.f / (1.f + expf(-(acc[m * 2] + bv)));
        sb2 += 1.f / (1.f + expf(-(acc[m * 2 + 1] + bv)));
    }
    g_mod[b * HW + i * WW + ja] = sa * (1.f / 9.f);
    g_mod[b * HW + i * WW + jb] = sb2 * (1.f / 9.f);
}

// ---------------------------------------------------------------------------
// K2: bilinear sampling + contraction + modulation + bias
// Block: 256 threads, tile 8x8 = 64 pixels. Grid (16,16,B).
// Per k: sample 64c x 64p into smem, then GEMM:
//   thread (o = tid&63, pg = tid>>6) accumulates 16 pixels.
// ---------------------------------------------------------------------------
__global__ __launch_bounds__(256) void k_main(
    const float* __restrict__ x,
    const float* __restrict__ bias,
    float* __restrict__ out)
{
    __shared__ float s_off[18 * 64];
    __shared__ float s_mod[64];
    __shared__ float s_samp[64 * 64];   // [c][p]
    __shared__ float s_w[64 * 64];      // [c][o] for current k

    int tid = threadIdx.x;
    int b = blockIdx.z;
    int i0 = blockIdx.y * 8;
    int j0 = blockIdx.x * 8;

    // load per-tile offsets and modulation
    const float* offb = g_off + (size_t)b * 18 * HW;
    for (int idx = tid; idx < 18 * 64; idx += 256) {
        int ch = idx >> 6, p = idx & 63;
        int py = p >> 3, px = p & 7;
        s_off[idx] = offb[ch * HW + (i0 + py) * WW + (j0 + px)];
    }
    if (tid < 64) {
        int py = tid >> 3, px = tid & 7;
        s_mod[tid] = g_mod[b * HW + (i0 + py) * WW + (j0 + px)];
    }

    float acc[16];
#pragma unroll
    for (int q = 0; q < 16; q++) acc[q] = 0.f;

    int o  = tid & 63;
    int pg = tid >> 6;
    const float* xb = x + (size_t)b * CC * HW;

    // sampling thread mapping: fixed pixel p, 16 channels (c0 + 4s)
    int sp = tid & 63;
    int sc0 = tid >> 6;
    int spy = sp >> 3, spx = sp & 7;

    for (int k = 0; k < 9; k++) {
        __syncthreads();   // previous-iteration consumers done; s_off ready (k=0)

        // stage transposed weight slice [c][o] (16 KB), coalesced float4
        {
            const float4* wsrc = (const float4*)(g_wT + k * CC * OO);
            float4* wdst = (float4*)s_w;
            for (int idx = tid; idx < 1024; idx += 256) wdst[idx] = wsrc[idx];
        }

        // bilinear sampling: setup once per (k,p), loop 16 channels
        {
            float ky = (float)(k / 3 - 1);
            float kx = (float)(k % 3 - 1);
            float sy = (float)(i0 + spy) + ky + s_off[k * 64 + sp];
            float sx = (float)(j0 + spx) + kx + s_off[(9 + k) * 64 + sp];
            float y0f = floorf(sy), x0f = floorf(sx);
            float wy1 = sy - y0f, wy0 = 1.f - wy1;
            float wx1 = sx - x0f, wx0 = 1.f - wx1;
            int y0 = (int)y0f, x0i = (int)x0f;
            bool yi0 = (y0 >= 0)      && (y0 < HH);
            bool yi1 = (y0 + 1 >= 0)  && (y0 + 1 < HH);
            bool xi0 = (x0i >= 0)     && (x0i < WW);
            bool xi1 = (x0i + 1 >= 0) && (x0i + 1 < WW);
            bool m00 = yi0 && xi0, m01 = yi0 && xi1;
            bool m10 = yi1 && xi0, m11 = yi1 && xi1;
            float w00 = wy0 * wx0, w01 = wy0 * wx1;
            float w10 = wy1 * wx0, w11 = wy1 * wx1;
            int base = y0 * WW + x0i;   // only dereferenced when masked in

#pragma unroll 4
            for (int s = 0; s < 16; s++) {
                int c = sc0 + s * 4;
                const float* xc = xb + c * HW;
                float v = 0.f;
                if (m00) v = fmaf(w00, __ldg(xc + base),          v);
                if (m01) v = fmaf(w01, __ldg(xc + base + 1),      v);
                if (m10) v = fmaf(w10, __ldg(xc + base + WW),     v);
                if (m11) v = fmaf(w11, __ldg(xc + base + WW + 1), v);
                s_samp[c * 64 + sp] = v;
            }
        }
        __syncthreads();

        // GEMM partial: acc[p-quad][o] += s_samp[c][p] * wT[c][o]
#pragma unroll 2
        for (int c = 0; c < CC; c++) {
            float wv = s_w[c * 64 + o];
#pragma unroll
            for (int q = 0; q < 4; q++) {
                float4 v = *(const float4*)&s_samp[c * 64 + q * 16 + pg * 4];
                acc[q * 4 + 0] = fmaf(wv, v.x, acc[q * 4 + 0]);
                acc[q * 4 + 1] = fmaf(wv, v.y, acc[q * 4 + 1]);
                acc[q * 4 + 2] = fmaf(wv, v.z, acc[q * 4 + 2]);
                acc[q * 4 + 3] = fmaf(wv, v.w, acc[q * 4 + 3]);
            }
        }
    }

    // epilogue: modulate + bias, write out[b][o][i][j]
    float bo = bias[o];
    float* outb = out + ((size_t)b * OO + o) * HW;
#pragma unroll
    for (int q = 0; q < 4; q++) {
#pragma unroll
        for (int r = 0; r < 4; r++) {
            int p = q * 16 + pg * 4 + r;
            int py = p >> 3, px = p & 7;
            outb[(i0 + py) * WW + (j0 + px)] = acc[q * 4 + r] * s_mod[p] + bo;
        }
    }
}

// ---------------------------------------------------------------------------
extern "C" void kernel_launch(void* const* d_in, const int* in_sizes, int n_in,
                              void* d_out, int out_size) {
    const float* x    = (const float*)d_in[0];   // (4,64,128,128)
    const float* w    = (const float*)d_in[1];   // (64,64,3,3)
    const float* bias = (const float*)d_in[2];   // (64,)
    const float* ow   = (const float*)d_in[3];   // (18,64,3,3)
    const float* ob   = (const float*)d_in[4];   // (18,)
    const float* mw   = (const float*)d_in[5];   // (9,64,3,3)
    const float* mb   = (const float*)d_in[6];   // (9,)
    float* out = (float*)d_out;

    k_transpose<<<144, 256>>>(w);
    k_offmod<<<dim3(4, 8, 4), 256>>>(x, ow, ob, mw, mb);
    k_main<<<dim3(16, 16, 4), 256>>>(x, bias, out);
}

// round 4
// speedup vs baseline: 2.6873x; 2.6873x over previous
#include <cuda_runtime.h>
#include <math.h>
#include <stdint.h>

#define HH 128
#define WW 128
#define CC 64
#define OO 64
#define BB 4
#define HW (HH*WW)

// Scratch (no allocations allowed)
__device__ float g_xT[(size_t)BB * HW * CC];   // NHWC x
__device__ float g_wT[9 * 64 * 64];            // [k][c][o], tf32-rounded
__device__ float g_wOM[9 * 64 * 32];           // [k][c][n] n<27 used, tf32-rounded
__device__ float g_off[(size_t)BB * 18 * HW];  // offsets [b][18][H][W]
__device__ float g_mod[(size_t)BB * HW];       // mod_mean [b][H][W]

// ---------------------------------------------------------------------------
__device__ __forceinline__ float tf32r(float v) {
    uint32_t u;
    asm("cvt.rna.tf32.f32 %0, %1;" : "=r"(u) : "f"(v));
    return __uint_as_float(u);
}

__device__ __forceinline__ void mma8(float* d,
    uint32_t a0, uint32_t a1, uint32_t a2, uint32_t a3,
    uint32_t b0, uint32_t b1)
{
    asm volatile("mma.sync.aligned.m16n8k8.row.col.f32.tf32.tf32.f32 "
        "{%0,%1,%2,%3}, {%4,%5,%6,%7}, {%8,%9}, {%0,%1,%2,%3};"
        : "+f"(d[0]), "+f"(d[1]), "+f"(d[2]), "+f"(d[3])
        : "r"(a0), "r"(a1), "r"(a2), "r"(a3), "r"(b0), "r"(b1));
}

// ---------------------------------------------------------------------------
// K_xt: NCHW -> NHWC transpose of x. One block per (h, b).
// ---------------------------------------------------------------------------
__global__ __launch_bounds__(256) void k_xt(const float* __restrict__ x) {
    __shared__ float s[128 * 68];
    int h = blockIdx.x, b = blockIdx.y;
    int tid = threadIdx.x, lane = tid & 31, wid = tid >> 5;

    const float* xb = x + (size_t)b * CC * HW + h * WW;
#pragma unroll
    for (int wc = 0; wc < 4; wc++) {
        int w = wc * 32 + lane;
#pragma unroll
        for (int cc = 0; cc < 8; cc++) {
            int c = wid * 8 + cc;
            s[w * 68 + c] = __ldg(xb + (size_t)c * HW + w);
        }
    }
    __syncthreads();
    float4* dst = (float4*)(g_xT + (size_t)(b * HH + h) * WW * CC);
    for (int i = tid; i < 2048; i += 256) {
        int w = i >> 4, c4 = (i & 15) << 2;
        dst[i] = *(float4*)&s[w * 68 + c4];
    }
}

// ---------------------------------------------------------------------------
// K_wprep: build tf32-rounded GEMM weight layouts.
// g_wT[k][c][o] from weight[o][c][k]; g_wOM[k][c][n] from offset_w/mod_w.
// ---------------------------------------------------------------------------
__global__ void k_wprep(const float* __restrict__ w,
                        const float* __restrict__ ow,
                        const float* __restrict__ mw)
{
    int idx = blockIdx.x * 256 + threadIdx.x;
    if (idx < 9 * 64 * 64) {
        int k = idx >> 12, c = (idx >> 6) & 63, o = idx & 63;
        g_wT[idx] = tf32r(w[(o * 64 + c) * 9 + k]);
    } else if (idx < 9 * 64 * 64 + 9 * 64 * 32) {
        int i2 = idx - 9 * 64 * 64;
        int k = i2 >> 11, c = (i2 >> 5) & 63, n = i2 & 31;
        float v = 0.f;
        if (n < 18)      v = ow[(n * 64 + c) * 9 + k];
        else if (n < 27) v = mw[((n - 18) * 64 + c) * 9 + k];
        g_wOM[(k * 64 + c) * 32 + n] = tf32r(v);
    }
}

// ---------------------------------------------------------------------------
// K_offmod: offsets + modulation as GEMM. M=128 px, N=32 (27 used), K=576.
// Per tap: shifted-window A fill from NHWC x, then mma.sync tf32.
// ---------------------------------------------------------------------------
__global__ __launch_bounds__(256) void k_offmod(
    const float* __restrict__ ob_, const float* __restrict__ mb_)
{
    __shared__ float s_A[128 * 68];   // reused as s_out[32][129] after GEMM
    __shared__ float s_W[64 * 40];

    int tid = threadIdx.x, lane = tid & 31, wid = tid >> 5;
    int r = lane >> 2, q = lane & 3;
    int b = blockIdx.z, i0 = blockIdx.y * 16, j0 = blockIdx.x * 8;
    const float* xT = g_xT + (size_t)b * HW * CC;

    float acc[16];
#pragma unroll
    for (int i = 0; i < 16; i++) acc[i] = 0.f;

    for (int k = 0; k < 9; k++) {
        __syncthreads();
        // stage W tile [64][32] -> stride 40
        {
            const float4* ws = (const float4*)(g_wOM + k * 2048);
            for (int i2 = tid; i2 < 512; i2 += 256) {
                int c = i2 >> 3, n4 = (i2 & 7) << 2;
                *(float4*)&s_W[c * 40 + n4] = ws[i2];
            }
        }
        // A fill: warp handles 16 pixels; lane covers 2 channels
        int dy = k / 3 - 1, dx = k % 3 - 1;
#pragma unroll 4
        for (int t = 0; t < 16; t++) {
            int p = wid * 16 + t;
            int y = i0 + (p >> 3) + dy;
            int xx = j0 + (p & 7) + dx;
            float2 v = make_float2(0.f, 0.f);
            if ((unsigned)y < HH && (unsigned)xx < WW)
                v = *(const float2*)(xT + ((size_t)y * WW + xx) * CC + 2 * lane);
            v.x = tf32r(v.x); v.y = tf32r(v.y);
            *(float2*)&s_A[p * 68 + 2 * lane] = v;
        }
        __syncthreads();
        // GEMM: M16 per warp, N32, K64
        int m0 = wid * 16;
#pragma unroll
        for (int kc = 0; kc < 8; kc++) {
            const float* Ab = s_A + (m0 + r) * 68 + kc * 8 + q;
            uint32_t a0 = __float_as_uint(Ab[0]);
            uint32_t a1 = __float_as_uint(Ab[8 * 68]);
            uint32_t a2 = __float_as_uint(Ab[4]);
            uint32_t a3 = __float_as_uint(Ab[8 * 68 + 4]);
            const float* Bb = s_W + (kc * 8 + q) * 40 + r;
#pragma unroll
            for (int nt = 0; nt < 4; nt++) {
                uint32_t b0 = __float_as_uint(Bb[nt * 8]);
                uint32_t b1 = __float_as_uint(Bb[4 * 40 + nt * 8]);
                mma8(acc + nt * 4, a0, a1, a2, a3, b0, b1);
            }
        }
    }
    __syncthreads();
    // stage D -> s_out[n][p], stride 129
    {
        float* s_out = s_A;
        int m0 = wid * 16;
#pragma unroll
        for (int nt = 0; nt < 4; nt++) {
            int n = nt * 8 + 2 * q;
            s_out[n * 129 + m0 + r]           = acc[nt * 4 + 0];
            s_out[(n + 1) * 129 + m0 + r]     = acc[nt * 4 + 1];
            s_out[n * 129 + m0 + r + 8]       = acc[nt * 4 + 2];
            s_out[(n + 1) * 129 + m0 + r + 8] = acc[nt * 4 + 3];
        }
    }
    __syncthreads();
    // write offsets + modulation mean
    {
        const float* s_out = s_A;
        float* offb = g_off + (size_t)b * 18 * HW;
        for (int i2 = tid; i2 < 18 * 128; i2 += 256) {
            int ch = i2 >> 7, p = i2 & 127;
            offb[ch * HW + (i0 + (p >> 3)) * WW + j0 + (p & 7)] =
                s_out[ch * 129 + p] + __ldg(ob_ + ch);
        }
        if (tid < 128) {
            int p = tid;
            float s = 0.f;
#pragma unroll
            for (int m2 = 0; m2 < 9; m2++) {
                float vv = s_out[(18 + m2) * 129 + p] + __ldg(mb_ + m2);
                s += 1.f / (1.f + expf(-vv));
            }
            g_mod[(size_t)b * HW + (i0 + (p >> 3)) * WW + j0 + (p & 7)] = s * (1.f / 9.f);
        }
    }
}

// ---------------------------------------------------------------------------
// K_main: bilinear sampling (NHWC, float2-per-lane) + mma.sync tf32 GEMM.
// Tile 128 px (16x8). M=128, N=64, K=576. Epilogue: *mod_mean + bias.
// smem (dynamic): s_off[2304] | s_mod[128] | s_A[128*68] | s_W[64*72]
// ---------------------------------------------------------------------------
#define SM_OFF 0
#define SM_MOD 2304
#define SM_A   2432
#define SM_W   11136
#define SM_FLOATS 15744
#define SM_BYTES (SM_FLOATS * 4)

__global__ __launch_bounds__(256) void k_main(
    const float* __restrict__ bias, float* __restrict__ out)
{
    extern __shared__ float sm[];
    float* s_off = sm + SM_OFF;
    float* s_mod = sm + SM_MOD;
    float* s_A   = sm + SM_A;
    float* s_W   = sm + SM_W;

    int tid = threadIdx.x, lane = tid & 31, wid = tid >> 5;
    int r = lane >> 2, q = lane & 3;
    int b = blockIdx.z, i0 = blockIdx.y * 16, j0 = blockIdx.x * 8;

    // load per-tile offsets + modulation
    const float* offb = g_off + (size_t)b * 18 * HW;
    for (int i2 = tid; i2 < 2304; i2 += 256) {
        int ch = i2 >> 7, p = i2 & 127;
        s_off[i2] = offb[ch * HW + (i0 + (p >> 3)) * WW + j0 + (p & 7)];
    }
    if (tid < 128)
        s_mod[tid] = g_mod[(size_t)b * HW + (i0 + (tid >> 3)) * WW + j0 + (tid & 7)];

    float acc[32];
#pragma unroll
    for (int i = 0; i < 32; i++) acc[i] = 0.f;

    const float* xT = g_xT + (size_t)b * HW * CC;

    for (int k = 0; k < 9; k++) {
        __syncthreads();
        // stage W tile [64][64] -> stride 72
        {
            const float4* ws = (const float4*)(g_wT + k * 4096);
            for (int i2 = tid; i2 < 1024; i2 += 256) {
                int c = i2 >> 4, o4 = (i2 & 15) << 2;
                *(float4*)&s_W[c * 72 + o4] = ws[i2];
            }
        }
        // bilinear sampling: warp handles 16 pixels, lane = 2 channels
        float fdy = (float)(k / 3 - 1), fdx = (float)(k % 3 - 1);
#pragma unroll 2
        for (int t = 0; t < 16; t++) {
            int p = wid * 16 + t;
            float sy = (float)(i0 + (p >> 3)) + fdy + s_off[k * 128 + p];
            float sx = (float)(j0 + (p & 7)) + fdx + s_off[(9 + k) * 128 + p];
            float y0f = floorf(sy), x0f = floorf(sx);
            float wy1 = sy - y0f, wx1 = sx - x0f;
            float wy0 = 1.f - wy1, wx0 = 1.f - wx1;
            int y0 = (int)y0f, x0 = (int)x0f;
            bool yi0 = (unsigned)y0 < HH;
            bool yi1 = (unsigned)(y0 + 1) < HH;
            bool xi0 = (unsigned)x0 < WW;
            bool xi1 = (unsigned)(x0 + 1) < WW;
            const float* base = xT + ((size_t)y0 * WW + x0) * CC + 2 * lane;
            float ax = 0.f, ay = 0.f;
            if (yi0 && xi0) { float2 v = *(const float2*)(base);
                float w00 = wy0 * wx0; ax = fmaf(w00, v.x, ax); ay = fmaf(w00, v.y, ay); }
            if (yi0 && xi1) { float2 v = *(const float2*)(base + CC);
                float w01 = wy0 * wx1; ax = fmaf(w01, v.x, ax); ay = fmaf(w01, v.y, ay); }
            if (yi1 && xi0) { float2 v = *(const float2*)(base + WW * CC);
                float w10 = wy1 * wx0; ax = fmaf(w10, v.x, ax); ay = fmaf(w10, v.y, ay); }
            if (yi1 && xi1) { float2 v = *(const float2*)(base + WW * CC + CC);
                float w11 = wy1 * wx1; ax = fmaf(w11, v.x, ax); ay = fmaf(w11, v.y, ay); }
            float2 o2; o2.x = tf32r(ax); o2.y = tf32r(ay);
            *(float2*)&s_A[p * 68 + 2 * lane] = o2;
        }
        __syncthreads();
        // GEMM: warp -> M32 x N32.  m0=(wid&3)*32, n0=(wid>>2)*32
        int m0 = (wid & 3) * 32, n0 = (wid >> 2) * 32;
#pragma unroll
        for (int kc = 0; kc < 8; kc++) {
            uint32_t a[2][4];
#pragma unroll
            for (int mt = 0; mt < 2; mt++) {
                const float* Ab = s_A + (m0 + mt * 16 + r) * 68 + kc * 8 + q;
                a[mt][0] = __float_as_uint(Ab[0]);
                a[mt][1] = __float_as_uint(Ab[8 * 68]);
                a[mt][2] = __float_as_uint(Ab[4]);
                a[mt][3] = __float_as_uint(Ab[8 * 68 + 4]);
            }
            const float* Bb = s_W + (kc * 8 + q) * 72 + n0 + r;
#pragma unroll
            for (int nt = 0; nt < 4; nt++) {
                uint32_t b0 = __float_as_uint(Bb[nt * 8]);
                uint32_t b1 = __float_as_uint(Bb[4 * 72 + nt * 8]);
                mma8(acc + (0 * 4 + nt) * 4, a[0][0], a[0][1], a[0][2], a[0][3], b0, b1);
                mma8(acc + (4 + nt) * 4,     a[1][0], a[1][1], a[1][2], a[1][3], b0, b1);
            }
        }
    }

    // epilogue: modulate + bias, direct register writes
    {
        int m0 = (wid & 3) * 32, n0 = (wid >> 2) * 32;
        float* outb = out + (size_t)b * OO * HW;
#pragma unroll
        for (int mt = 0; mt < 2; mt++) {
#pragma unroll
            for (int half = 0; half < 2; half++) {
                int p = m0 + mt * 16 + r + half * 8;
                float modp = s_mod[p];
                int oy = (i0 + (p >> 3)) * WW + j0 + (p & 7);
#pragma unroll
                for (int nt = 0; nt < 4; nt++) {
                    int o = n0 + nt * 8 + 2 * q;
                    float d0 = acc[(mt * 4 + nt) * 4 + half * 2 + 0];
                    float d1 = acc[(mt * 4 + nt) * 4 + half * 2 + 1];
                    outb[(size_t)o * HW + oy]       = fmaf(d0, modp, __ldg(bias + o));
                    outb[(size_t)(o + 1) * HW + oy] = fmaf(d1, modp, __ldg(bias + o + 1));
                }
            }
        }
    }
}

// ---------------------------------------------------------------------------
extern "C" void kernel_launch(void* const* d_in, const int* in_sizes, int n_in,
                              void* d_out, int out_size) {
    const float* x    = (const float*)d_in[0];
    const float* w    = (const float*)d_in[1];
    const float* bias = (const float*)d_in[2];
    const float* ow   = (const float*)d_in[3];
    const float* ob   = (const float*)d_in[4];
    const float* mw   = (const float*)d_in[5];
    const float* mb   = (const float*)d_in[6];
    float* out = (float*)d_out;

    static int inited = 0;
    if (!inited) {
        cudaFuncSetAttribute(k_main, cudaFuncAttributeMaxDynamicSharedMemorySize, SM_BYTES);
        inited = 1;
    }

    k_xt<<<dim3(HH, BB), 256>>>(x);
    k_wprep<<<216, 256>>>(w, ow, mw);
    k_offmod<<<dim3(16, 8, 4), 256>>>(ob, mb);
    k_main<<<dim3(16, 8, 4), 256, SM_BYTES>>>(bias, out);
}